// round 15
// baseline (speedup 1.0000x reference)
#include <cuda_runtime.h>

// QuantizedBKCore: B x N tridiagonal resolvent diagonal at z = i.
// Windowed continued-fraction scan in linear (p/q Moebius) form.
// R15: c1 path smem layout rework. a staged as packed float2 pairs ->
// one conflict-free LDS.64 feeds two steps (sweep LDS instr and
// wavefronts both halved vs .x-only 2-way-conflicted LDS.32). G bounce
// as float4 with j+(j>>3) padding -> 8 conflict-free STS.128/LDS.128.
// Math identical to R14 (Wronskian combine). Boundary path unchanged.

#define KCH   16
#define WARM  16
#define CPB   128
#define SEG   (CPB * KCH)         // 2048
#define REGN  (SEG + 2 * WARM)    // 2080
#define PADI(i) ((i) + ((i) >> 4))
#define PADG(i) ((i) + ((i) >> 3))
#define SMEMN (PADI(REGN - 1) + 1)            // general: float2 slots
#define NP    (REGN / 2)                      // 1040 a-pairs
#define NSA   (PADI(NP - 1) + 1)              // padded a-pair slots
#define SA_BYTES (((NSA * 8) + 15) & ~15)
#define NSG   (PADG(SEG / 2 - 1) + 1)         // padded G-float4 slots
#define GEN_BYTES (SMEMN * 8)
#define C1_BYTES  (SA_BYTES + NSG * 16)
#define SM_BYTES  (C1_BYTES > GEN_BYTES ? C1_BYTES : GEN_BYTES)

#define RN_THR 1048576.0f            /* 2^20  */
#define RN_SCL 9.5367431640625e-07f  /* 2^-20 */

// he = clip(hd + clip(round(v),-128,127), -10, 10); clips dead in-regime.
__device__ __forceinline__ float he_val(float v, float hdv) {
    return rintf(v) + hdv;
}

// General step: p' = c*q ; q' = (z - a)*q - p, z = i.
__device__ __forceinline__ void lin_step(float a, float c,
                                         float& pr, float& pi,
                                         float& qr, float& qi) {
    float t1  = qi + pr;
    float nqr = fmaf(-a, qr, -t1);
    float t2  = qr - pi;
    float nqi = fmaf(-a, qi, t2);
    float npr = c * qr;
    float npi = c * qi;
    pr = npr; pi = npi; qr = nqr; qi = nqi;
}

// c==1 step: p' = q ; q' = (z - a)*q - p.
__device__ __forceinline__ void lin_step1(float a,
                                          float& or_, float& oi_,
                                          float& qr, float& qi) {
    float t1  = qi + or_;
    float nqr = fmaf(-a, qr, -t1);
    float t2  = qr - oi_;
    float nqi = fmaf(-a, qi, t2);
    or_ = qr; oi_ = qi; qr = nqr; qi = nqi;
}

__device__ __forceinline__ void renorm(float& pr, float& pi,
                                       float& qr, float& qi) {
    float m = fabsf(qr) + fabsf(qi);
    float s = (m > RN_THR) ? RN_SCL : 1.0f;
    pr *= s; pi *= s; qr *= s; qi *= s;
}

// Scale chain so |q| ~ 1 (ratios are scale-invariant).
__device__ __forceinline__ void normalize(float& pr, float& pi,
                                          float& qr, float& qi) {
    float s = __fdividef(1.0f, fabsf(qr) + fabsf(qi));
    pr *= s; pi *= s; qr *= s; qi *= s;
}

__global__ void __launch_bounds__(CPB, 8) bk_kernel(
    const float* __restrict__ v, const float* __restrict__ hd,
    const float* __restrict__ sub, const float* __restrict__ sup,
    float* __restrict__ out, int N, int segs_per_row)
{
    __shared__ __align__(16) char smraw[SM_BYTES];

    int blk  = blockIdx.x;
    int b    = blk / segs_per_row;
    int seg  = blk - b * segs_per_row;
    int seg0 = seg * SEG;
    int tid  = threadIdx.x;
    const float* vr = v + (size_t)b * N;
    float* orow = out + ((size_t)b * N + seg0) * 2;

    int lb = WARM + tid * KCH;        // even
    int hb = lb / 2;                  // a-pair base = 8 + 8*tid

    bool c1 = (seg0 >= WARM) && (seg0 + SEG + WARM <= N);

    if (c1) {
        // ================= unit-coupling fast path (interior) =================
        float2* sa  = reinterpret_cast<float2*>(smraw);           // a-pairs
        float4* sg4 = reinterpret_cast<float4*>(smraw + SA_BYTES); // G quads

        // Staging: 4 elements -> 2 a-pair STS.64
        for (int m = tid * 4; m < REGN; m += CPB * 4) {
            int g = seg0 - WARM + m;                  // multiple of 4
            float4 vv = *reinterpret_cast<const float4*>(vr + g);
            float4 hh = *reinterpret_cast<const float4*>(hd + g);
            sa[PADI(m / 2)]     = make_float2(he_val(vv.x, hh.x),
                                              he_val(vv.y, hh.y));
            sa[PADI(m / 2 + 1)] = make_float2(he_val(vv.z, hh.z),
                                              he_val(vv.w, hh.w));
        }
        __syncthreads();

        // Fused warm-up (ILP = 2), pair loads.
        // Backward args: a[lb+31] .. a[lb+17] (15 steps), carry a[lb+16].
        // Forward  args: a[lb-16] .. a[lb-1]  (16 steps).
        float bor = 0.0f, boi = 0.0f, bqr = 1.0f, bqi = 0.0f;
        float for_ = 0.0f, foi = 0.0f, fqr = 1.0f, fqi = 0.0f;
        float2 bw = sa[PADI(hb + 15)];                // (a[lb+30], a[lb+31])
        float an = bw.y;
#pragma unroll
        for (int jp = 0; jp < 7; ++jp) {
            float2 fw = sa[PADI(hb - 8 + jp)];
            lin_step1(fw.x, for_, foi, fqr, fqi);
            lin_step1(fw.y, for_, foi, fqr, fqi);
            lin_step1(an,   bor, boi, bqr, bqi);
            lin_step1(bw.x, bor, boi, bqr, bqi);
            bw = sa[PADI(hb + 14 - jp)];
            an = bw.y;
        }
        {
            float2 fw = sa[PADI(hb - 1)];
            lin_step1(fw.x, for_, foi, fqr, fqi);
            lin_step1(fw.y, for_, foi, fqr, fqi);
            lin_step1(an,   bor, boi, bqr, bqi);      // arg a[lb+17]
            an = bw.x;                                // carry a[lb+16]
        }
        normalize(bor, boi, bqr, bqi);
        normalize(for_, foi, fqr, fqi);
        __syncthreads();   // neighbor (warm) reads done

        // Backward in-chunk: 2 steps per pair, store raw q pairs
        float Qr[KCH], Qi[KCH];
#pragma unroll
        for (int kk = 7; kk >= 0; --kk) {
            float2 f2 = sa[PADI(hb + kk)];            // (a[lb+2kk], a[lb+2kk+1])
            lin_step1(an, bor, boi, bqr, bqi);
            Qr[2 * kk + 1] = bqr; Qi[2 * kk + 1] = bqi;
            an = f2.y;
            lin_step1(an, bor, boi, bqr, bqi);
            Qr[2 * kk] = bqr;     Qi[2 * kk] = bqi;
            an = f2.x;
        }
        lin_step1(an, bor, boi, bqr, bqi);            // q at site lb-1
        float Qm1r = bqr, Qm1i = bqi;

        // Wronskian: W = Q_{-1}*qF_0 - pF_0*Q_0 (constant over k)
        float Wr = fmaf(Qm1r, fqr, fmaf(-Qm1i, fqi,
                   fmaf(-for_, Qr[0],  foi * Qi[0])));
        float Wi = fmaf(Qm1r, fqi, fmaf( Qm1i, fqr,
                   fmaf(-for_, Qi[0], -foi * Qr[0])));
        float nW  = fmaf(Wr, Wr, Wi * Wi);
        float inW = __fdividef(1.0f, nW);
        float iwr =  Wr * inW;
        float iwi = -Wi * inW;

        // Combine: G_k = (qF_k * Q_k) * conj(W)/|W|^2 ; quad STS.128 out
        int obq = tid * (KCH / 2);                    // G-quad base
#pragma unroll
        for (int kk = 0; kk < 8; ++kk) {
            float2 f2 = sa[PADI(hb + kk)];
            int k0 = 2 * kk;
            float T0r = fmaf(fqr, Qr[k0], -fqi * Qi[k0]);
            float T0i = fmaf(fqr, Qi[k0],  fqi * Qr[k0]);
            float G0r = rintf(fmaf(T0r, iwr, -T0i * iwi));
            float G0i = rintf(fmaf(T0r, iwi,  T0i * iwr));
            lin_step1(f2.x, for_, foi, fqr, fqi);
            float T1r = fmaf(fqr, Qr[k0 + 1], -fqi * Qi[k0 + 1]);
            float T1i = fmaf(fqr, Qi[k0 + 1],  fqi * Qr[k0 + 1]);
            float G1r = rintf(fmaf(T1r, iwr, -T1i * iwi));
            float G1i = rintf(fmaf(T1r, iwi,  T1i * iwr));
            if (kk < 7) lin_step1(f2.y, for_, foi, fqr, fqi);
            sg4[PADG(obq + kk)] = make_float4(G0r, G0i, G1r, G1i);
        }
        __syncthreads();

        // Coalesced output: conflict-free LDS.128 -> STG.128
        for (int li = tid; li < SEG / 2; li += CPB) {
            float4 o = sg4[PADG(li)];
            *reinterpret_cast<float4*>(orow + li * 4) = o;
        }
        return;
    }

    // ==================== General path (boundary blocks) ====================
    float2* sac = reinterpret_cast<float2*>(smraw);
    float Rr[KCH], Ri[KCH];
    for (int m = tid * 4; m < REGN; m += CPB * 4) {
        int g = seg0 - WARM + m;                      // multiple of 4
        if (g >= 0 && g + 4 < N) {                    // sub/sup[g+3] in range
            float4 vv = *reinterpret_cast<const float4*>(vr + g);
            float4 hh = *reinterpret_cast<const float4*>(hd + g);
            float4 s1 = *reinterpret_cast<const float4*>(sub + g);
            float4 s2 = *reinterpret_cast<const float4*>(sup + g);
            sac[PADI(m + 0)] = make_float2(he_val(vv.x, hh.x), s1.x * s2.x);
            sac[PADI(m + 1)] = make_float2(he_val(vv.y, hh.y), s1.y * s2.y);
            sac[PADI(m + 2)] = make_float2(he_val(vv.z, hh.z), s1.z * s2.z);
            sac[PADI(m + 3)] = make_float2(he_val(vv.w, hh.w), s1.w * s2.w);
        } else {
            for (int j = 0; j < 4; ++j) {
                int mm = m + j;
                if (mm >= REGN) break;
                int gg = seg0 - WARM + mm;
                float a = 0.0f, c = 0.0f;
                if (gg >= 0 && gg < N) {
                    a = he_val(__ldg(vr + gg), __ldg(hd + gg));
                    c = (gg < N - 1) ? __ldg(sub + gg) * __ldg(sup + gg) : 0.0f;
                }
                sac[PADI(mm)] = make_float2(a, c);
            }
        }
    }
    __syncthreads();

    float bpr = 0.0f, bpi = 0.0f, bqr = 1.0f, bqi = 0.0f;
    float fpr = 0.0f, fpi = 0.0f, fqr = 1.0f, fqi = 0.0f;
    int itop = lb + KCH - 1 + WARM;
    float an = sac[PADI(itop)].x;
#pragma unroll
    for (int j = 0; j < WARM; ++j) {
        if (j < WARM - 1) {
            float2 f = sac[PADI(itop - 1 - j)];
            lin_step(an, f.y, bpr, bpi, bqr, bqi);
            an = f.x;
        }
        {
            float2 g = sac[PADI(lb - WARM + j)];
            lin_step(g.x, g.y, fpr, fpi, fqr, fqi);
        }
        if ((j & 7) == 7) {
            renorm(bpr, bpi, bqr, bqi);
            renorm(fpr, fpi, fqr, fqi);
        }
    }
    renorm(bpr, bpi, bqr, bqi);
    renorm(fpr, fpi, fqr, fqi);
    __syncthreads();   // neighbor (warm) reads done; chunk slots now private

#pragma unroll
    for (int k = KCH - 1; k >= 0; --k) {
        float2 f = sac[PADI(lb + k)];
        lin_step(an, f.y, bpr, bpi, bqr, bqi);
        an = f.x;
        float n   = fmaf(bqr, bqr, bqi * bqi);
        float inv = __fdividef(1.0f, n);
        Rr[k] = fmaf(bpr, bqr,  bpi * bqi) * inv;
        Ri[k] = fmaf(bpi, bqr, -bpr * bqi) * inv;
        if ((k & 7) == 0) renorm(bpr, bpi, bqr, bqi);
    }

#pragma unroll
    for (int k = 0; k < KCH; ++k) {
        float2 f  = sac[PADI(lb + k)];
        float wr  = -f.x - Rr[k];
        float wi  = 1.0f - Ri[k];
        float Dr  = fmaf(wr, fqr, fmaf(-wi, fqi, -fpr));
        float Di  = fmaf(wr, fqi, fmaf( wi, fqr, -fpi));
        float n   = fmaf(Dr, Dr, Di * Di);
        float inv = __fdividef(1.0f, n);
        float Gr  = rintf(fmaf(fqr, Dr,  fqi * Di) * inv);
        float Gi  = rintf(fmaf(fqi, Dr, -fqr * Di) * inv);
        if (k < KCH - 1) {
            lin_step(f.x, f.y, fpr, fpi, fqr, fqi);
            if ((k & 7) == 7) renorm(fpr, fpi, fqr, fqi);
        }
        sac[PADI(lb + k)] = make_float2(Gr, Gi);
    }
    __syncthreads();

    int lim = min(SEG, N - seg0);
    for (int li = 2 * tid; li < lim; li += 2 * CPB) {
        float2 g0 = sac[PADI(WARM + li)];
        float2 g1 = sac[PADI(WARM + li + 1)];
        *reinterpret_cast<float4*>(orow + li * 2) =
            make_float4(g0.x, g0.y, g1.x, g1.y);
    }
}

extern "C" void kernel_launch(void* const* d_in, const int* in_sizes, int n_in,
                              void* d_out, int out_size) {
    const float* v   = (const float*)d_in[0];   // (B, N) float32
    const float* hd  = (const float*)d_in[1];   // (N,)   float32
    const float* sub = (const float*)d_in[2];   // (N-1,) float32
    const float* sup = (const float*)d_in[3];   // (N-1,) float32
    int N = in_sizes[1];
    int B = in_sizes[0] / N;

    int segs_per_row = (N + SEG - 1) / SEG;
    int grid = B * segs_per_row;
    bk_kernel<<<grid, CPB>>>(v, hd, sub, sup, (float*)d_out, N, segs_per_row);
}

// round 16
// speedup vs baseline: 1.0061x; 1.0061x over previous
#include <cuda_runtime.h>

// QuantizedBKCore: B x N tridiagonal resolvent diagonal at z = i.
// Windowed continued-fraction scan in linear (p/q Moebius) form.
// R16: depth-2 software-pipelined LDS in all c1 sweep loops (at the
// 64-reg cap ptxas cannot hoist; load-to-use was ~16 chain-cyc < 29-cyc
// LDS latency -> exposed stalls on the serial chain). Post-warm barrier
// removed (sa read-only after staging; combine writes only the separate
// G region). Math identical to R14/R15 (Wronskian combine).

#define KCH   16
#define WARM  16
#define CPB   128
#define SEG   (CPB * KCH)         // 2048
#define REGN  (SEG + 2 * WARM)    // 2080
#define PADI(i) ((i) + ((i) >> 4))
#define PADG(i) ((i) + ((i) >> 3))
#define SMEMN (PADI(REGN - 1) + 1)            // general: float2 slots
#define NP    (REGN / 2)                      // 1040 a-pairs
#define NSA   (PADI(NP - 1) + 1)
#define SA_BYTES (((NSA * 8) + 15) & ~15)
#define NSG   (PADG(SEG / 2 - 1) + 1)
#define GEN_BYTES (SMEMN * 8)
#define C1_BYTES  (SA_BYTES + NSG * 16)
#define SM_BYTES  (C1_BYTES > GEN_BYTES ? C1_BYTES : GEN_BYTES)

#define RN_THR 1048576.0f            /* 2^20  */
#define RN_SCL 9.5367431640625e-07f  /* 2^-20 */

// he = clip(hd + clip(round(v),-128,127), -10, 10); clips dead in-regime.
__device__ __forceinline__ float he_val(float v, float hdv) {
    return rintf(v) + hdv;
}

// General step: p' = c*q ; q' = (z - a)*q - p, z = i.
__device__ __forceinline__ void lin_step(float a, float c,
                                         float& pr, float& pi,
                                         float& qr, float& qi) {
    float t1  = qi + pr;
    float nqr = fmaf(-a, qr, -t1);
    float t2  = qr - pi;
    float nqi = fmaf(-a, qi, t2);
    float npr = c * qr;
    float npi = c * qi;
    pr = npr; pi = npi; qr = nqr; qi = nqi;
}

// c==1 step: p' = q ; q' = (z - a)*q - p.
__device__ __forceinline__ void lin_step1(float a,
                                          float& or_, float& oi_,
                                          float& qr, float& qi) {
    float t1  = qi + or_;
    float nqr = fmaf(-a, qr, -t1);
    float t2  = qr - oi_;
    float nqi = fmaf(-a, qi, t2);
    or_ = qr; oi_ = qi; qr = nqr; qi = nqi;
}

__device__ __forceinline__ void renorm(float& pr, float& pi,
                                       float& qr, float& qi) {
    float m = fabsf(qr) + fabsf(qi);
    float s = (m > RN_THR) ? RN_SCL : 1.0f;
    pr *= s; pi *= s; qr *= s; qi *= s;
}

// Scale chain so |q| ~ 1 (ratios are scale-invariant).
__device__ __forceinline__ void normalize(float& pr, float& pi,
                                          float& qr, float& qi) {
    float s = __fdividef(1.0f, fabsf(qr) + fabsf(qi));
    pr *= s; pi *= s; qr *= s; qi *= s;
}

__global__ void __launch_bounds__(CPB, 8) bk_kernel(
    const float* __restrict__ v, const float* __restrict__ hd,
    const float* __restrict__ sub, const float* __restrict__ sup,
    float* __restrict__ out, int N, int segs_per_row)
{
    __shared__ __align__(16) char smraw[SM_BYTES];

    int blk  = blockIdx.x;
    int b    = blk / segs_per_row;
    int seg  = blk - b * segs_per_row;
    int seg0 = seg * SEG;
    int tid  = threadIdx.x;
    const float* vr = v + (size_t)b * N;
    float* orow = out + ((size_t)b * N + seg0) * 2;

    int lb = WARM + tid * KCH;        // even
    int hb = lb / 2;                  // a-pair base = 8 + 8*tid

    bool c1 = (seg0 >= WARM) && (seg0 + SEG + WARM <= N);

    if (c1) {
        // ================= unit-coupling fast path (interior) =================
        float2* sa  = reinterpret_cast<float2*>(smraw);            // a-pairs
        float4* sg4 = reinterpret_cast<float4*>(smraw + SA_BYTES); // G quads

        // Staging: 4 elements -> 2 a-pair STS.64
        for (int m = tid * 4; m < REGN; m += CPB * 4) {
            int g = seg0 - WARM + m;                  // multiple of 4
            float4 vv = *reinterpret_cast<const float4*>(vr + g);
            float4 hh = *reinterpret_cast<const float4*>(hd + g);
            sa[PADI(m / 2)]     = make_float2(he_val(vv.x, hh.x),
                                              he_val(vv.y, hh.y));
            sa[PADI(m / 2 + 1)] = make_float2(he_val(vv.z, hh.z),
                                              he_val(vv.w, hh.w));
        }
        __syncthreads();

        // Fused warm-up (ILP = 2), depth-2 prefetched pair loads.
        // Backward args: a[lb+31] .. a[lb+17] (15 steps), carry a[lb+16].
        // Forward  args: a[lb-16] .. a[lb-1]  (16 steps).
        float bor = 0.0f, boi = 0.0f, bqr = 1.0f, bqi = 0.0f;
        float for_ = 0.0f, foi = 0.0f, fqr = 1.0f, fqi = 0.0f;
        float2 bw  = sa[PADI(hb + 15)];               // (a[lb+30], a[lb+31])
        float2 fw  = sa[PADI(hb - 8)];                // (a[lb-16], a[lb-15])
        float2 bwn = sa[PADI(hb + 14)];
        float2 fwn = sa[PADI(hb - 7)];
        float an = bw.y;
#pragma unroll
        for (int jp = 0; jp < 7; ++jp) {
            lin_step1(fw.x, for_, foi, fqr, fqi);
            lin_step1(fw.y, for_, foi, fqr, fqi);
            lin_step1(an,   bor, boi, bqr, bqi);
            lin_step1(bw.x, bor, boi, bqr, bqi);
            bw = bwn; fw = fwn; an = bw.y;
            if (jp < 6) {
                bwn = sa[PADI(hb + 13 - jp)];
                fwn = sa[PADI(hb - 6 + jp)];
            }
        }
        // tail: fw = pair(hb-1) = (a[lb-2], a[lb-1]); bw = pair(hb+8); an = a[lb+17]
        lin_step1(fw.x, for_, foi, fqr, fqi);
        lin_step1(fw.y, for_, foi, fqr, fqi);
        lin_step1(an,   bor, boi, bqr, bqi);
        an = bw.x;                                    // carry a[lb+16]
        normalize(bor, boi, bqr, bqi);
        normalize(for_, foi, fqr, fqi);
        // (no barrier: sa is read-only from here; combine writes sg4 only)

        // Backward in-chunk: 2 steps per pair, depth-2 prefetch, raw q pairs
        float Qr[KCH], Qi[KCH];
        float2 f2  = sa[PADI(hb + 7)];
        float2 f2n = sa[PADI(hb + 6)];
#pragma unroll
        for (int kk = 7; kk >= 0; --kk) {
            lin_step1(an, bor, boi, bqr, bqi);
            Qr[2 * kk + 1] = bqr; Qi[2 * kk + 1] = bqi;
            an = f2.y;
            lin_step1(an, bor, boi, bqr, bqi);
            Qr[2 * kk] = bqr;     Qi[2 * kk] = bqi;
            an = f2.x;
            f2 = f2n;
            if (kk >= 2) f2n = sa[PADI(hb + kk - 2)];
        }
        lin_step1(an, bor, boi, bqr, bqi);            // q at site lb-1
        float Qm1r = bqr, Qm1i = bqi;

        // Wronskian: W = Q_{-1}*qF_0 - pF_0*Q_0 (constant over k)
        float Wr = fmaf(Qm1r, fqr, fmaf(-Qm1i, fqi,
                   fmaf(-for_, Qr[0],  foi * Qi[0])));
        float Wi = fmaf(Qm1r, fqi, fmaf( Qm1i, fqr,
                   fmaf(-for_, Qi[0], -foi * Qr[0])));
        float nW  = fmaf(Wr, Wr, Wi * Wi);
        float inW = __fdividef(1.0f, nW);
        float iwr =  Wr * inW;
        float iwi = -Wi * inW;

        // Combine: G_k = (qF_k * Q_k) * conj(W)/|W|^2 ; depth-2 prefetch
        int obq = tid * (KCH / 2);                    // G-quad base
        f2  = sa[PADI(hb + 0)];
        f2n = sa[PADI(hb + 1)];
#pragma unroll
        for (int kk = 0; kk < 8; ++kk) {
            int k0 = 2 * kk;
            float T0r = fmaf(fqr, Qr[k0], -fqi * Qi[k0]);
            float T0i = fmaf(fqr, Qi[k0],  fqi * Qr[k0]);
            float G0r = rintf(fmaf(T0r, iwr, -T0i * iwi));
            float G0i = rintf(fmaf(T0r, iwi,  T0i * iwr));
            lin_step1(f2.x, for_, foi, fqr, fqi);
            float T1r = fmaf(fqr, Qr[k0 + 1], -fqi * Qi[k0 + 1]);
            float T1i = fmaf(fqr, Qi[k0 + 1],  fqi * Qr[k0 + 1]);
            float G1r = rintf(fmaf(T1r, iwr, -T1i * iwi));
            float G1i = rintf(fmaf(T1r, iwi,  T1i * iwr));
            if (kk < 7) lin_step1(f2.y, for_, foi, fqr, fqi);
            f2 = f2n;
            if (kk < 6) f2n = sa[PADI(hb + kk + 2)];
            sg4[PADG(obq + kk)] = make_float4(G0r, G0i, G1r, G1i);
        }
        __syncthreads();

        // Coalesced output: conflict-free LDS.128 -> STG.128
        for (int li = tid; li < SEG / 2; li += CPB) {
            float4 o = sg4[PADG(li)];
            *reinterpret_cast<float4*>(orow + li * 4) = o;
        }
        return;
    }

    // ==================== General path (boundary blocks) ====================
    float2* sac = reinterpret_cast<float2*>(smraw);
    float Rr[KCH], Ri[KCH];
    for (int m = tid * 4; m < REGN; m += CPB * 4) {
        int g = seg0 - WARM + m;                      // multiple of 4
        if (g >= 0 && g + 4 < N) {                    // sub/sup[g+3] in range
            float4 vv = *reinterpret_cast<const float4*>(vr + g);
            float4 hh = *reinterpret_cast<const float4*>(hd + g);
            float4 s1 = *reinterpret_cast<const float4*>(sub + g);
            float4 s2 = *reinterpret_cast<const float4*>(sup + g);
            sac[PADI(m + 0)] = make_float2(he_val(vv.x, hh.x), s1.x * s2.x);
            sac[PADI(m + 1)] = make_float2(he_val(vv.y, hh.y), s1.y * s2.y);
            sac[PADI(m + 2)] = make_float2(he_val(vv.z, hh.z), s1.z * s2.z);
            sac[PADI(m + 3)] = make_float2(he_val(vv.w, hh.w), s1.w * s2.w);
        } else {
            for (int j = 0; j < 4; ++j) {
                int mm = m + j;
                if (mm >= REGN) break;
                int gg = seg0 - WARM + mm;
                float a = 0.0f, c = 0.0f;
                if (gg >= 0 && gg < N) {
                    a = he_val(__ldg(vr + gg), __ldg(hd + gg));
                    c = (gg < N - 1) ? __ldg(sub + gg) * __ldg(sup + gg) : 0.0f;
                }
                sac[PADI(mm)] = make_float2(a, c);
            }
        }
    }
    __syncthreads();

    float bpr = 0.0f, bpi = 0.0f, bqr = 1.0f, bqi = 0.0f;
    float fpr = 0.0f, fpi = 0.0f, fqr = 1.0f, fqi = 0.0f;
    int itop = lb + KCH - 1 + WARM;
    float an = sac[PADI(itop)].x;
#pragma unroll
    for (int j = 0; j < WARM; ++j) {
        if (j < WARM - 1) {
            float2 f = sac[PADI(itop - 1 - j)];
            lin_step(an, f.y, bpr, bpi, bqr, bqi);
            an = f.x;
        }
        {
            float2 g = sac[PADI(lb - WARM + j)];
            lin_step(g.x, g.y, fpr, fpi, fqr, fqi);
        }
        if ((j & 7) == 7) {
            renorm(bpr, bpi, bqr, bqi);
            renorm(fpr, fpi, fqr, fqi);
        }
    }
    renorm(bpr, bpi, bqr, bqi);
    renorm(fpr, fpi, fqr, fqi);
    __syncthreads();   // neighbor (warm) reads done; chunk slots now private

#pragma unroll
    for (int k = KCH - 1; k >= 0; --k) {
        float2 f = sac[PADI(lb + k)];
        lin_step(an, f.y, bpr, bpi, bqr, bqi);
        an = f.x;
        float n   = fmaf(bqr, bqr, bqi * bqi);
        float inv = __fdividef(1.0f, n);
        Rr[k] = fmaf(bpr, bqr,  bpi * bqi) * inv;
        Ri[k] = fmaf(bpi, bqr, -bpr * bqi) * inv;
        if ((k & 7) == 0) renorm(bpr, bpi, bqr, bqi);
    }

#pragma unroll
    for (int k = 0; k < KCH; ++k) {
        float2 f  = sac[PADI(lb + k)];
        float wr  = -f.x - Rr[k];
        float wi  = 1.0f - Ri[k];
        float Dr  = fmaf(wr, fqr, fmaf(-wi, fqi, -fpr));
        float Di  = fmaf(wr, fqi, fmaf( wi, fqr, -fpi));
        float n   = fmaf(Dr, Dr, Di * Di);
        float inv = __fdividef(1.0f, n);
        float Gr  = rintf(fmaf(fqr, Dr,  fqi * Di) * inv);
        float Gi  = rintf(fmaf(fqi, Dr, -fqr * Di) * inv);
        if (k < KCH - 1) {
            lin_step(f.x, f.y, fpr, fpi, fqr, fqi);
            if ((k & 7) == 7) renorm(fpr, fpi, fqr, fqi);
        }
        sac[PADI(lb + k)] = make_float2(Gr, Gi);
    }
    __syncthreads();

    int lim = min(SEG, N - seg0);
    for (int li = 2 * tid; li < lim; li += 2 * CPB) {
        float2 g0 = sac[PADI(WARM + li)];
        float2 g1 = sac[PADI(WARM + li + 1)];
        *reinterpret_cast<float4*>(orow + li * 2) =
            make_float4(g0.x, g0.y, g1.x, g1.y);
    }
}

extern "C" void kernel_launch(void* const* d_in, const int* in_sizes, int n_in,
                              void* d_out, int out_size) {
    const float* v   = (const float*)d_in[0];   // (B, N) float32
    const float* hd  = (const float*)d_in[1];   // (N,)   float32
    const float* sub = (const float*)d_in[2];   // (N-1,) float32
    const float* sup = (const float*)d_in[3];   // (N-1,) float32
    int N = in_sizes[1];
    int B = in_sizes[0] / N;

    int segs_per_row = (N + SEG - 1) / SEG;
    int grid = B * segs_per_row;
    bk_kernel<<<grid, CPB>>>(v, hd, sub, sup, (float*)d_out, N, segs_per_row);
}